// round 4
// baseline (speedup 1.0000x reference)
#include <cuda_runtime.h>
#include <cuda_bf16.h>
#include <cstdint>

// ---------------------------------------------------------------------------
// BiLSTM: B=32, T=512, D=512, H=512. out = [B,T,2H] fp32.
// Phase 1: xg[dir][t][g][b] = x @ W_ih^T + b_ih + b_hh   (SGEMM, FFMA2)
// Phase 2: persistent recurrent scan, FFMA2, custom grid barrier (128 blocks)
// ---------------------------------------------------------------------------

#define B_  32
#define T_  512
#define D_  512
#define H_  512
#define G4  2048          // 4*H
#define NB  128           // persistent blocks in scan kernel

// Scratch (device globals: allocation-free rule)
__device__ float g_xg[2][T_][G4][B_];      // 268 MB, [dir][t][gate*H+j][b]
__device__ float g_h[2][2][H_][B_];        // [buf][dir][j][b]
__device__ volatile unsigned g_bar;

// ---------------------------------------------------------------------------
// f32x2 packed-math helpers (FFMA2: 2x fp32 FMA throughput, PTX-only path)
// ---------------------------------------------------------------------------
__device__ __forceinline__ unsigned long long pack2(float x, float y) {
    unsigned long long r;
    asm("mov.b64 %0, {%1, %2};" : "=l"(r)
        : "r"(__float_as_uint(x)), "r"(__float_as_uint(y)));
    return r;
}
__device__ __forceinline__ void ffma2(unsigned long long& d,
                                      unsigned long long a,
                                      unsigned long long b) {
    asm("fma.rn.f32x2 %0, %1, %2, %0;" : "+l"(d) : "l"(a), "l"(b));
}
__device__ __forceinline__ float2 unpack2(unsigned long long v) {
    unsigned lo, hi;
    asm("mov.b64 {%0, %1}, %2;" : "=r"(lo), "=r"(hi) : "l"(v));
    return make_float2(__uint_as_float(lo), __uint_as_float(hi));
}

// fast activations (MUFU EX2 based; overflow-safe)
__device__ __forceinline__ float sigf(float x) {
    return __fdividef(1.f, 1.f + __expf(-x));
}
__device__ __forceinline__ float tanhfast(float x) {
    float ax = fabsf(x);
    float e  = __expf(-2.f * ax);           // in (0,1], no overflow
    float t  = __fdividef(1.f - e, 1.f + e);
    return copysignf(t, x);
}

// ---------------------------------------------------------------------------
// Init: zero h state + barrier counter (must run every launch)
// ---------------------------------------------------------------------------
__global__ void init_kernel() {
    int idx = blockIdx.x * blockDim.x + threadIdx.x;
    if (idx == 0) *(unsigned*)&g_bar = 0u;
    float* p = &g_h[0][0][0][0];
    if (idx < 2 * 2 * H_ * B_) p[idx] = 0.f;
}

// ---------------------------------------------------------------------------
// Phase 1: C[M=16384, N=4096] = X[16384,512] * W^T, W row-major [N,K]
// 128x128 tile, K-chunk 8, 256 threads, 8x8 micro-tile, FFMA2 pairs along N.
// ---------------------------------------------------------------------------
__global__ __launch_bounds__(256, 2) void proj_kernel(
    const float* __restrict__ x,
    const float* __restrict__ Wf, const float* __restrict__ Wb,
    const float* __restrict__ bihf, const float* __restrict__ bhhf,
    const float* __restrict__ bihb, const float* __restrict__ bhhb)
{
    __shared__ __align__(16) float As[8][128];
    __shared__ __align__(16) float Bs[8][128];

    const int tid = threadIdx.x;
    const int tx  = tid & 15;        // n micro index (8 cols -> 4 pairs)
    const int ty  = tid >> 4;        // m micro index
    const int m0  = blockIdx.y * 128;
    const int n0  = blockIdx.x * 128;
    const int dir = n0 >> 11;        // 2048-column halves
    const int ng0 = n0 & 2047;
    const float* W   = dir ? Wb : Wf;
    const float* bih = dir ? bihb : bihf;
    const float* bhh = dir ? bhhb : bhhf;

    const int la_m = tid >> 1;           // 0..127
    const int la_k = (tid & 1) << 2;     // 0 or 4

    const float* Aptr = x + (size_t)(m0 + la_m) * D_ + la_k;
    const float* Bptr = W + (size_t)(ng0 + la_m) * D_ + la_k;

    unsigned long long acc2[8][4];
#pragma unroll
    for (int i = 0; i < 8; i++)
#pragma unroll
        for (int j = 0; j < 4; j++) acc2[i][j] = 0ULL;

    for (int k0 = 0; k0 < D_; k0 += 8) {
        float4 av = *(const float4*)(Aptr + k0);
        float4 bv = *(const float4*)(Bptr + k0);
        As[la_k + 0][la_m] = av.x; As[la_k + 1][la_m] = av.y;
        As[la_k + 2][la_m] = av.z; As[la_k + 3][la_m] = av.w;
        Bs[la_k + 0][la_m] = bv.x; Bs[la_k + 1][la_m] = bv.y;
        Bs[la_k + 2][la_m] = bv.z; Bs[la_k + 3][la_m] = bv.w;
        __syncthreads();
#pragma unroll
        for (int kk = 0; kk < 8; kk++) {
            float4 a0 = *(const float4*)&As[kk][ty * 8];
            float4 a1 = *(const float4*)&As[kk][ty * 8 + 4];
            ulonglong2 bA = *(const ulonglong2*)&Bs[kk][tx * 8];
            ulonglong2 bB = *(const ulonglong2*)&Bs[kk][tx * 8 + 4];
            const unsigned long long bp0 = bA.x, bp1 = bA.y;
            const unsigned long long bp2 = bB.x, bp3 = bB.y;
            float a[8] = {a0.x, a0.y, a0.z, a0.w, a1.x, a1.y, a1.z, a1.w};
#pragma unroll
            for (int i = 0; i < 8; i++) {
                unsigned long long ap = pack2(a[i], a[i]);
                ffma2(acc2[i][0], ap, bp0);
                ffma2(acc2[i][1], ap, bp1);
                ffma2(acc2[i][2], ap, bp2);
                ffma2(acc2[i][3], ap, bp3);
            }
        }
        __syncthreads();
    }

#pragma unroll
    for (int jp = 0; jp < 4; jp++) {
        int g0 = ng0 + tx * 8 + jp * 2;
        float bias0 = bih[g0] + bhh[g0];
        float bias1 = bih[g0 + 1] + bhh[g0 + 1];
#pragma unroll
        for (int i = 0; i < 8; i++) {
            int m = m0 + ty * 8 + i;
            int bb_ = m >> 9;       // batch
            int t   = m & 511;      // time
            float2 v = unpack2(acc2[i][jp]);
            g_xg[dir][t][g0][bb_]     = v.x + bias0;
            g_xg[dir][t][g0 + 1][bb_] = v.y + bias1;
        }
    }
}

// ---------------------------------------------------------------------------
// Grid barrier (all NB blocks co-resident; fenced monotonic counter)
// ---------------------------------------------------------------------------
__device__ __forceinline__ void grid_sync(unsigned target) {
    __threadfence();
    __syncthreads();
    if (threadIdx.x == 0) {
        atomicAdd((unsigned*)&g_bar, 1u);
        while (g_bar < target) { }
        __threadfence();
    }
    __syncthreads();
}

// ---------------------------------------------------------------------------
// Phase 2: persistent recurrent scan, FFMA2.
// 128 blocks = 2 dirs x 64 j-tiles(8). 128 threads = 4 jt x 32 b; each thread
// computes 2 j columns (8 gate dots) per h load -> issue==fma at 8 cyc/k/SMSP.
// W_hh slice cached in SMEM once; h double-buffered in global via L2 (cg ops).
// ---------------------------------------------------------------------------
__global__ __launch_bounds__(128, 1) void lstm_scan_kernel(
    const int*   __restrict__ lengths,
    const float* __restrict__ Whf,
    const float* __restrict__ Whb,
    float*       __restrict__ out)
{
    extern __shared__ float smem[];
    float* W_s = smem;            // 16384 floats: [jl][k][gate4]
    float* h_s = smem + 16384;    // 16384 floats: [k][b]

    const int tid = threadIdx.x;
    const int b   = tid & 31;
    const int jt  = tid >> 5;               // 0..3 (one warp per jt)
    const int bx  = blockIdx.x;
    const int dir = bx >> 6;
    const int j0  = (bx & 63) << 3;
    const int jA  = j0 + jt * 2;
    const int jB  = jA + 1;
    const float* W = dir ? Whb : Whf;

    // Fill W_s once: W_s[(jj*512 + k)*4 + gate] = W[(gate*512 + j0+jj)*512 + k]
    for (int idx = tid; idx < 8 * 4 * 512; idx += 128) {
        int jj   = idx >> 11;
        int rem  = idx & 2047;
        int gate = rem >> 9;
        int k    = rem & 511;
        W_s[(((jj << 9) + k) << 2) + gate] = W[(((gate << 9) + j0 + jj) << 9) + k];
    }

    const int len = lengths[b];
    float hA = 0.f, cA = 0.f, hB = 0.f, cB = 0.f;
    int cur = 0;
    // per-(jl,k) gate quad = one ulonglong2 = ((W_i,W_f),(W_g,W_o))
    const ulonglong2* WpA = (const ulonglong2*)W_s + ((jt * 2 + 0) << 9);
    const ulonglong2* WpB = (const ulonglong2*)W_s + ((jt * 2 + 1) << 9);
    unsigned target = 0;

    for (int s = 0; s < T_; s++) {
        target += NB;
        grid_sync(target);   // prev-step h visible; guards W_s fill (s=0) and h_s reuse

        // load h: 16384 floats = 4096 float4, 128 threads -> 32 iterations
        // (L2 via __ldcg — custom barrier doesn't invalidate L1)
        const float4* hg = (const float4*)&g_h[cur][dir][0][0];
#pragma unroll
        for (int i = 0; i < 32; i++)
            ((float4*)h_s)[tid + (i << 7)] = __ldcg(hg + tid + (i << 7));
        __syncthreads();

        const int t = dir ? (T_ - 1 - s) : s;

        // prefetch gate pre-activations (DRAM latency hidden behind dot loop)
        const float* xgp = &g_xg[dir][t][0][0];
        float xiA = xgp[((0 << 9) + jA) * 32 + b];
        float xfA = xgp[((1 << 9) + jA) * 32 + b];
        float xgA = xgp[((2 << 9) + jA) * 32 + b];
        float xoA = xgp[((3 << 9) + jA) * 32 + b];
        float xiB = xgp[((0 << 9) + jB) * 32 + b];
        float xfB = xgp[((1 << 9) + jB) * 32 + b];
        float xgB = xgp[((2 << 9) + jB) * 32 + b];
        float xoB = xgp[((3 << 9) + jB) * 32 + b];

        unsigned long long aifA = 0ULL, agoA = 0ULL;
        unsigned long long aifB = 0ULL, agoB = 0ULL;
#pragma unroll 4
        for (int k = 0; k < H_; k++) {
            float hv = h_s[(k << 5) + b];        // conflict-free (lane = b)
            unsigned long long hp = pack2(hv, hv);
            ulonglong2 wA = WpA[k];              // LDS.128 broadcast (warp-uniform)
            ulonglong2 wB = WpB[k];
            ffma2(aifA, hp, wA.x);
            ffma2(agoA, hp, wA.y);
            ffma2(aifB, hp, wB.x);
            ffma2(agoB, hp, wB.y);
        }

        float2 vifA = unpack2(aifA), vgoA = unpack2(agoA);
        float2 vifB = unpack2(aifB), vgoB = unpack2(agoB);

        {
            float ig = sigf(vifA.x + xiA);
            float fg = sigf(vifA.y + xfA);
            float gg = tanhfast(vgoA.x + xgA);
            float og = sigf(vgoA.y + xoA);
            float cn = fg * cA + ig * gg;
            float hn = og * tanhfast(cn);
            if (t < len) { cA = cn; hA = hn; }
        }
        {
            float ig = sigf(vifB.x + xiB);
            float fg = sigf(vifB.y + xfB);
            float gg = tanhfast(vgoB.x + xgB);
            float og = sigf(vgoB.y + xoB);
            float cn = fg * cB + ig * gg;
            float hn = og * tanhfast(cn);
            if (t < len) { cB = cn; hB = hn; }
        }

        __stcg(&g_h[cur ^ 1][dir][jA][b], hA);
        __stcg(&g_h[cur ^ 1][dir][jB][b], hB);
        size_t obase = ((size_t)b * T_ + t) * (2 * H_) + (dir << 9);
        out[obase + jA] = hA;
        out[obase + jB] = hB;
        cur ^= 1;
    }
}

// ---------------------------------------------------------------------------
extern "C" void kernel_launch(void* const* d_in, const int* in_sizes, int n_in,
                              void* d_out, int out_size)
{
    const float* x      = (const float*)d_in[0];
    const int*   lens   = (const int*)  d_in[1];
    const float* Wihf   = (const float*)d_in[2];
    const float* Whhf   = (const float*)d_in[3];
    const float* bihf   = (const float*)d_in[4];
    const float* bhhf   = (const float*)d_in[5];
    const float* Wihb   = (const float*)d_in[6];
    const float* Whhb   = (const float*)d_in[7];
    const float* bihb   = (const float*)d_in[8];
    const float* bhhb   = (const float*)d_in[9];
    float* out = (float*)d_out;

    cudaFuncSetAttribute(lstm_scan_kernel,
                         cudaFuncAttributeMaxDynamicSharedMemorySize, 131072);

    init_kernel<<<256, 256>>>();

    dim3 pg(4096 / 128, 16384 / 128);   // (N tiles, M tiles)
    proj_kernel<<<pg, 256>>>(x, Wihf, Wihb, bihf, bhhf, bihb, bhhb);

    lstm_scan_kernel<<<NB, 128, 131072>>>(lens, Whhf, Whhb, out);
}

// round 6
// speedup vs baseline: 1.5536x; 1.5536x over previous
#include <cuda_runtime.h>
#include <cstdint>

// ---------------------------------------------------------------------------
// BiLSTM: B=32, T=512, D=512, H=512. out = [B,T,2H] fp32.
// Phase 1: mma.sync tf32 GEMM  xg = W_ih @ x^T (+bias)   [sm_80 PTX path]
// Phase 2: persistent recurrent scan (proven config), grid barrier
// ---------------------------------------------------------------------------

#define B_  32
#define T_  512
#define D_  512
#define H_  512
#define G4  2048          // 4*H
#define NB  128           // persistent blocks in scan kernel

// Scratch (device globals: allocation-free rule)
__device__ float g_xg[2][T_][G4][B_];      // 268 MB, [dir][t][gate*H+j][b]
__device__ float g_h[2][2][H_][B_];        // [buf][dir][j][b]
__device__ volatile unsigned g_bar;

// ---------------------------------------------------------------------------
__device__ __forceinline__ uint32_t f2tf32(float f) {
    uint32_t r;
    asm("cvt.rna.tf32.f32 %0, %1;" : "=r"(r) : "f"(f));
    return r;
}

__device__ __forceinline__ void mma_tf32(float* c, const uint32_t* a, const uint32_t* b) {
    asm volatile(
        "mma.sync.aligned.m16n8k8.row.col.f32.tf32.tf32.f32 "
        "{%0,%1,%2,%3}, {%4,%5,%6,%7}, {%8,%9}, {%0,%1,%2,%3};"
        : "+f"(c[0]), "+f"(c[1]), "+f"(c[2]), "+f"(c[3])
        : "r"(a[0]), "r"(a[1]), "r"(a[2]), "r"(a[3]), "r"(b[0]), "r"(b[1]));
}

// fast activations (MUFU EX2 based; overflow-safe) — validated in R4
__device__ __forceinline__ float sigf(float x) {
    return __fdividef(1.f, 1.f + __expf(-x));
}
__device__ __forceinline__ float tanhfast(float x) {
    float ax = fabsf(x);
    float e  = __expf(-2.f * ax);
    float t  = __fdividef(1.f - e, 1.f + e);
    return copysignf(t, x);
}

// ---------------------------------------------------------------------------
// Phase 1: tf32 mma.sync GEMM.
// C[m = dir*2048+g, n' = dt*32+b] = sum_k W[g][k] * X[b*T+t0+dt][k]
// Block tile 128x128x32; 8 warps = 2 m-warps x 4 n-warps; warp tile 64x32.
// SMEM stride 136: frag banks 8*(lane%4)+lane/4 -> conflict-free.
// ---------------------------------------------------------------------------
#define SSTR 136            // smem row stride (floats) for [k][m] tiles
#define KCH  32             // K chunk

__global__ __launch_bounds__(256, 2) void proj_mma_kernel(
    const float* __restrict__ x,
    const float* __restrict__ Wf, const float* __restrict__ Wb,
    const float* __restrict__ bihf, const float* __restrict__ bhhf,
    const float* __restrict__ bihb, const float* __restrict__ bhhb)
{
    __shared__ __align__(16) float A_s[KCH * SSTR];   // [k][m] 17.4KB
    __shared__ __align__(16) float B_s[KCH * SSTR];   // [k][n] 17.4KB

    const int tid  = threadIdx.x;
    const int lane = tid & 31;
    const int wid  = tid >> 5;
    const int mw   = wid & 1;          // 0..1
    const int nw   = wid >> 1;         // 0..3 (== dt)

    // ---- folded init (block (0,0)): zero h buf 0 + barrier counter ----
    if (blockIdx.x == 0 && blockIdx.y == 0) {
        if (tid == 0) *(unsigned*)&g_bar = 0u;
        float4* hz = (float4*)&g_h[0][0][0][0];    // 16384 float4 total (both bufs)
#pragma unroll
        for (int i = 0; i < 32; i++)
            hz[tid + (i << 8)] = make_float4(0.f, 0.f, 0.f, 0.f);
    }

    const int mtile = blockIdx.y;          // 0..31
    const int dir   = mtile >> 4;
    const int mg0   = (mtile & 15) * 128;  // g base within dir
    const int t0    = blockIdx.x * 4;      // 4 timesteps per N-tile
    const float* W  = dir ? Wb : Wf;

    // gmem loader indices: row = tid>>1 (0..127), seg toggles with tid&1
    const int lrow = tid >> 1;
    const int lseg = tid & 1;
    const int bL   = lrow & 31;            // batch for B tile row
    const int dtL  = lrow >> 5;            // dt for B tile row
    const float* Arow = W + (size_t)(mg0 + lrow) * D_;
    const float* Brow = x + ((size_t)bL * T_ + t0 + dtL) * D_;

    float acc[4][4][4];
#pragma unroll
    for (int mi = 0; mi < 4; mi++)
#pragma unroll
        for (int ni = 0; ni < 4; ni++)
#pragma unroll
            for (int q = 0; q < 4; q++) acc[mi][ni][q] = 0.f;

    const int frag_k = lane & 3;           // k sub-index
    const int frag_r = lane >> 2;          // row sub-index

    for (int c = 0; c < D_ / KCH; c++) {
        const int kc = c * KCH;
        // load + cvt + transpose-store
#pragma unroll
        for (int it = 0; it < 4; it++) {
            int seg = it * 2 + lseg;       // 0..7 (16B segments)
            int k0  = seg * 4;
            float4 av = *(const float4*)(Arow + kc + k0);
            float4 bv = *(const float4*)(Brow + kc + k0);
            A_s[(k0 + 0) * SSTR + lrow] = __uint_as_float(f2tf32(av.x));
            A_s[(k0 + 1) * SSTR + lrow] = __uint_as_float(f2tf32(av.y));
            A_s[(k0 + 2) * SSTR + lrow] = __uint_as_float(f2tf32(av.z));
            A_s[(k0 + 3) * SSTR + lrow] = __uint_as_float(f2tf32(av.w));
            B_s[(k0 + 0) * SSTR + lrow] = __uint_as_float(f2tf32(bv.x));
            B_s[(k0 + 1) * SSTR + lrow] = __uint_as_float(f2tf32(bv.y));
            B_s[(k0 + 2) * SSTR + lrow] = __uint_as_float(f2tf32(bv.z));
            B_s[(k0 + 3) * SSTR + lrow] = __uint_as_float(f2tf32(bv.w));
        }
        __syncthreads();

#pragma unroll
        for (int ks = 0; ks < KCH / 8; ks++) {
            const int kb = ks * 8 + frag_k;
            uint32_t afr[4][4], bfr[4][2];
#pragma unroll
            for (int mi = 0; mi < 4; mi++) {
                int m = mw * 64 + mi * 16 + frag_r;
                afr[mi][0] = __float_as_uint(A_s[kb * SSTR + m]);
                afr[mi][1] = __float_as_uint(A_s[kb * SSTR + m + 8]);
                afr[mi][2] = __float_as_uint(A_s[(kb + 4) * SSTR + m]);
                afr[mi][3] = __float_as_uint(A_s[(kb + 4) * SSTR + m + 8]);
            }
#pragma unroll
            for (int ni = 0; ni < 4; ni++) {
                int n = nw * 32 + ni * 8 + frag_r;
                bfr[ni][0] = __float_as_uint(B_s[kb * SSTR + n]);
                bfr[ni][1] = __float_as_uint(B_s[(kb + 4) * SSTR + n]);
            }
#pragma unroll
            for (int mi = 0; mi < 4; mi++)
#pragma unroll
                for (int ni = 0; ni < 4; ni++)
                    mma_tf32(acc[mi][ni], afr[mi], bfr[ni]);
        }
        __syncthreads();
    }

    // ---- epilogue: +bias, float2 stores (b-contiguous) ----
    const int t  = t0 + nw;
    const int bc = 2 * (lane & 3);         // b col base within n-frag
#pragma unroll
    for (int mi = 0; mi < 4; mi++) {
        int g0 = mg0 + mw * 64 + mi * 16 + frag_r;   // rows g0, g0+8
        float bias0 = dir ? (bihb[g0] + bhhb[g0]) : (bihf[g0] + bhhf[g0]);
        float bias1 = dir ? (bihb[g0 + 8] + bhhb[g0 + 8]) : (bihf[g0 + 8] + bhhf[g0 + 8]);
#pragma unroll
        for (int ni = 0; ni < 4; ni++) {
            int b = ni * 8 + bc;
            *(float2*)&g_xg[dir][t][g0][b] =
                make_float2(acc[mi][ni][0] + bias0, acc[mi][ni][1] + bias0);
            *(float2*)&g_xg[dir][t][g0 + 8][b] =
                make_float2(acc[mi][ni][2] + bias1, acc[mi][ni][3] + bias1);
        }
    }
}

// ---------------------------------------------------------------------------
// Grid barrier (all NB blocks co-resident; fenced monotonic counter)
// ---------------------------------------------------------------------------
__device__ __forceinline__ void grid_sync(unsigned target) {
    __threadfence();
    __syncthreads();
    if (threadIdx.x == 0) {
        atomicAdd((unsigned*)&g_bar, 1u);
        while (g_bar < target) { }
        __threadfence();
    }
    __syncthreads();
}

// ---------------------------------------------------------------------------
// Phase 2: persistent recurrent scan (proven config).
// 128 blocks = 2 dirs x 64 j-tiles(8). 256 threads = 8 j x 32 b.
// ---------------------------------------------------------------------------
__global__ __launch_bounds__(256, 1) void lstm_scan_kernel(
    const int*   __restrict__ lengths,
    const float* __restrict__ Whf,
    const float* __restrict__ Whb,
    float*       __restrict__ out)
{
    extern __shared__ float smem[];
    float* W_s = smem;            // 16384 floats: [jl][k][gate4]
    float* h_s = smem + 16384;    // 16384 floats: [k][b]

    const int tid = threadIdx.x;
    const int b   = tid & 31;
    const int jl  = tid >> 5;               // 0..7
    const int bx  = blockIdx.x;
    const int dir = bx >> 6;
    const int j0  = (bx & 63) << 3;
    const int jglob = j0 + jl;
    const float* W = dir ? Whb : Whf;

    // Fill W_s once: W_s[(jj*512 + k)*4 + gate] = W[(gate*512 + j0+jj)*512 + k]
    for (int idx = tid; idx < 8 * 4 * 512; idx += 256) {
        int jj   = idx >> 11;
        int rem  = idx & 2047;
        int gate = rem >> 9;
        int k    = rem & 511;
        W_s[(((jj << 9) + k) << 2) + gate] = W[(((gate << 9) + j0 + jj) << 9) + k];
    }

    const int len = lengths[b];
    float h_reg = 0.f, c_reg = 0.f;
    int cur = 0;
    const float4* Wp = (const float4*)W_s + (jl << 9);
    unsigned target = 0;

    for (int s = 0; s < T_; s++) {
        target += NB;
        grid_sync(target);   // prev-step h visible; guards W_s fill (s=0) and h_s reuse

        // load h: 4096 float4 / 256 threads = 16 iters (L2 via __ldcg)
        const float4* hg = (const float4*)&g_h[cur][dir][0][0];
        float4* hs4 = (float4*)h_s;
#pragma unroll
        for (int i = 0; i < 16; i++)
            hs4[tid + (i << 8)] = __ldcg(hg + tid + (i << 8));
        __syncthreads();

        const int t = dir ? (T_ - 1 - s) : s;

        const float* xgp = &g_xg[dir][t][0][0];
        float xi = xgp[((0 << 9) + jglob) * 32 + b];
        float xf = xgp[((1 << 9) + jglob) * 32 + b];
        float xgv = xgp[((2 << 9) + jglob) * 32 + b];
        float xo = xgp[((3 << 9) + jglob) * 32 + b];

        float4 acc = make_float4(0.f, 0.f, 0.f, 0.f);
#pragma unroll 8
        for (int k = 0; k < H_; k++) {
            float hv = h_s[(k << 5) + b];       // conflict-free (lane = b)
            float4 w = Wp[k];                   // LDS.128 broadcast
            acc.x = fmaf(hv, w.x, acc.x);
            acc.y = fmaf(hv, w.y, acc.y);
            acc.z = fmaf(hv, w.z, acc.z);
            acc.w = fmaf(hv, w.w, acc.w);
        }

        float ig = sigf(acc.x + xi);
        float fg = sigf(acc.y + xf);
        float gg = tanhfast(acc.z + xgv);
        float og = sigf(acc.w + xo);
        float c_new = fg * c_reg + ig * gg;
        float h_new = og * tanhfast(c_new);
        if (t < len) { c_reg = c_new; h_reg = h_new; }   // mask: hold state

        __stcg(&g_h[cur ^ 1][dir][jglob][b], h_reg);
        out[((size_t)b * T_ + t) * (2 * H_) + (dir << 9) + jglob] = h_reg;
        cur ^= 1;
    }
}

// ---------------------------------------------------------------------------
extern "C" void kernel_launch(void* const* d_in, const int* in_sizes, int n_in,
                              void* d_out, int out_size)
{
    const float* x      = (const float*)d_in[0];
    const int*   lens   = (const int*)  d_in[1];
    const float* Wihf   = (const float*)d_in[2];
    const float* Whhf   = (const float*)d_in[3];
    const float* bihf   = (const float*)d_in[4];
    const float* bhhf   = (const float*)d_in[5];
    const float* Wihb   = (const float*)d_in[6];
    const float* Whhb   = (const float*)d_in[7];
    const float* bihb   = (const float*)d_in[8];
    const float* bhhb   = (const float*)d_in[9];
    float* out = (float*)d_out;

    cudaFuncSetAttribute(lstm_scan_kernel,
                         cudaFuncAttributeMaxDynamicSharedMemorySize, 131072);

    dim3 pg(T_ / 4, 32);   // (128 N-tiles of 4 timesteps, 32 M-tiles over 2 dirs)
    proj_mma_kernel<<<pg, 256>>>(x, Wihf, Wihb, bihf, bhhf, bihb, bhhb);

    lstm_scan_kernel<<<NB, 256, 131072>>>(lens, Whhf, Whhb, out);
}

// round 7
// speedup vs baseline: 2.7979x; 1.8009x over previous
#include <cuda_runtime.h>
#include <cuda_bf16.h>
#include <cstdint>

// ---------------------------------------------------------------------------
// BiLSTM: B=32, T=512, D=512, H=512. out = [B,T,2H] fp32.
// Phase 1: mma.sync tf32 GEMM  xg = W_ih @ x^T (+bias)
// Phase 2: persistent recurrent scan with bf16 split-precision mma.sync
//          (3-term: W0h0 + W0h1 + W1h0), grid barrier, 128 blocks
// ---------------------------------------------------------------------------

#define B_  32
#define T_  512
#define D_  512
#define H_  512
#define G4  2048          // 4*H
#define NB  128           // persistent blocks in scan kernel
#define SH  520           // scan smem bf16 row stride (pad: conflict-free ldmatrix)

// Scratch (device globals: allocation-free rule)
__device__ float g_xg[2][T_][G4][B_];             // [dir][t][gate*H+j][b]
__device__ __nv_bfloat16 g_h0[2][2][B_][H_];      // [buf][dir][b][j] hi plane
__device__ __nv_bfloat16 g_h1[2][2][B_][H_];      // [buf][dir][b][j] lo plane
__device__ volatile unsigned g_bar;

// ---------------------------------------------------------------------------
__device__ __forceinline__ uint32_t f2tf32(float f) {
    uint32_t r;
    asm("cvt.rna.tf32.f32 %0, %1;" : "=r"(r) : "f"(f));
    return r;
}
__device__ __forceinline__ void mma_tf32(float* c, const uint32_t* a, const uint32_t* b) {
    asm volatile(
        "mma.sync.aligned.m16n8k8.row.col.f32.tf32.tf32.f32 "
        "{%0,%1,%2,%3}, {%4,%5,%6,%7}, {%8,%9}, {%0,%1,%2,%3};"
        : "+f"(c[0]), "+f"(c[1]), "+f"(c[2]), "+f"(c[3])
        : "r"(a[0]), "r"(a[1]), "r"(a[2]), "r"(a[3]), "r"(b[0]), "r"(b[1]));
}
__device__ __forceinline__ void mma_bf16(float* c, const uint32_t* a, const uint32_t* b) {
    asm volatile(
        "mma.sync.aligned.m16n8k16.row.col.f32.bf16.bf16.f32 "
        "{%0,%1,%2,%3}, {%4,%5,%6,%7}, {%8,%9}, {%0,%1,%2,%3};"
        : "+f"(c[0]), "+f"(c[1]), "+f"(c[2]), "+f"(c[3])
        : "r"(a[0]), "r"(a[1]), "r"(a[2]), "r"(a[3]), "r"(b[0]), "r"(b[1]));
}
__device__ __forceinline__ void ldmx4(uint32_t* r, uint32_t addr) {
    asm volatile("ldmatrix.sync.aligned.m8n8.x4.shared.b16 {%0,%1,%2,%3}, [%4];"
        : "=r"(r[0]), "=r"(r[1]), "=r"(r[2]), "=r"(r[3]) : "r"(addr));
}
__device__ __forceinline__ void ldmx2(uint32_t* r, uint32_t addr) {
    asm volatile("ldmatrix.sync.aligned.m8n8.x2.shared.b16 {%0,%1}, [%2];"
        : "=r"(r[0]), "=r"(r[1]) : "r"(addr));
}
__device__ __forceinline__ uint32_t smem_u32(const void* p) {
    uint32_t a;
    asm("{ .reg .u64 t; cvta.to.shared.u64 t, %1; cvt.u32.u64 %0, t; }"
        : "=r"(a) : "l"(p));
    return a;
}
__device__ __forceinline__ uint16_t bfu(__nv_bfloat16 v) {
    return __bfloat16_as_ushort(v);
}

// fast activations (MUFU EX2 based; overflow-safe) — validated R4/R6
__device__ __forceinline__ float sigf(float x) {
    return __fdividef(1.f, 1.f + __expf(-x));
}
__device__ __forceinline__ float tanhfast(float x) {
    float ax = fabsf(x);
    float e  = __expf(-2.f * ax);
    float t  = __fdividef(1.f - e, 1.f + e);
    return copysignf(t, x);
}

// ---------------------------------------------------------------------------
// Phase 1: tf32 mma.sync GEMM (validated R6).
// C[m = dir*2048+g, n' = dt*32+b] = sum_k W[g][k] * X[b*T+t0+dt][k]
// ---------------------------------------------------------------------------
#define SSTR 136
#define KCH  32

__global__ __launch_bounds__(256, 2) void proj_mma_kernel(
    const float* __restrict__ x,
    const float* __restrict__ Wf, const float* __restrict__ Wb,
    const float* __restrict__ bihf, const float* __restrict__ bhhf,
    const float* __restrict__ bihb, const float* __restrict__ bhhb)
{
    __shared__ __align__(16) float A_s[KCH * SSTR];
    __shared__ __align__(16) float B_s[KCH * SSTR];

    const int tid  = threadIdx.x;
    const int lane = tid & 31;
    const int wid  = tid >> 5;
    const int mw   = wid & 1;
    const int nw   = wid >> 1;

    // ---- folded init (block (0,0)): zero h planes buf 0 + barrier counter ----
    if (blockIdx.x == 0 && blockIdx.y == 0) {
        if (tid == 0) *(unsigned*)&g_bar = 0u;
        uint4* z0 = (uint4*)&g_h0[0][0][0][0];   // 4096 uint4
        uint4* z1 = (uint4*)&g_h1[0][0][0][0];
#pragma unroll
        for (int i = 0; i < 16; i++) {
            z0[tid + (i << 8)] = make_uint4(0, 0, 0, 0);
            z1[tid + (i << 8)] = make_uint4(0, 0, 0, 0);
        }
    }

    const int mtile = blockIdx.y;
    const int dir   = mtile >> 4;
    const int mg0   = (mtile & 15) * 128;
    const int t0    = blockIdx.x * 4;
    const float* W  = dir ? Wb : Wf;

    const int lrow = tid >> 1;
    const int lseg = tid & 1;
    const int bL   = lrow & 31;
    const int dtL  = lrow >> 5;
    const float* Arow = W + (size_t)(mg0 + lrow) * D_;
    const float* Brow = x + ((size_t)bL * T_ + t0 + dtL) * D_;

    float acc[4][4][4];
#pragma unroll
    for (int mi = 0; mi < 4; mi++)
#pragma unroll
        for (int ni = 0; ni < 4; ni++)
#pragma unroll
            for (int q = 0; q < 4; q++) acc[mi][ni][q] = 0.f;

    const int frag_k = lane & 3;
    const int frag_r = lane >> 2;

    for (int c = 0; c < D_ / KCH; c++) {
        const int kc = c * KCH;
#pragma unroll
        for (int it = 0; it < 4; it++) {
            int seg = it * 2 + lseg;
            int k0  = seg * 4;
            float4 av = *(const float4*)(Arow + kc + k0);
            float4 bv = *(const float4*)(Brow + kc + k0);
            A_s[(k0 + 0) * SSTR + lrow] = __uint_as_float(f2tf32(av.x));
            A_s[(k0 + 1) * SSTR + lrow] = __uint_as_float(f2tf32(av.y));
            A_s[(k0 + 2) * SSTR + lrow] = __uint_as_float(f2tf32(av.z));
            A_s[(k0 + 3) * SSTR + lrow] = __uint_as_float(f2tf32(av.w));
            B_s[(k0 + 0) * SSTR + lrow] = __uint_as_float(f2tf32(bv.x));
            B_s[(k0 + 1) * SSTR + lrow] = __uint_as_float(f2tf32(bv.y));
            B_s[(k0 + 2) * SSTR + lrow] = __uint_as_float(f2tf32(bv.z));
            B_s[(k0 + 3) * SSTR + lrow] = __uint_as_float(f2tf32(bv.w));
        }
        __syncthreads();

#pragma unroll
        for (int ks = 0; ks < KCH / 8; ks++) {
            const int kb = ks * 8 + frag_k;
            uint32_t afr[4][4], bfr[4][2];
#pragma unroll
            for (int mi = 0; mi < 4; mi++) {
                int m = mw * 64 + mi * 16 + frag_r;
                afr[mi][0] = __float_as_uint(A_s[kb * SSTR + m]);
                afr[mi][1] = __float_as_uint(A_s[kb * SSTR + m + 8]);
                afr[mi][2] = __float_as_uint(A_s[(kb + 4) * SSTR + m]);
                afr[mi][3] = __float_as_uint(A_s[(kb + 4) * SSTR + m + 8]);
            }
#pragma unroll
            for (int ni = 0; ni < 4; ni++) {
                int n = nw * 32 + ni * 8 + frag_r;
                bfr[ni][0] = __float_as_uint(B_s[kb * SSTR + n]);
                bfr[ni][1] = __float_as_uint(B_s[(kb + 4) * SSTR + n]);
            }
#pragma unroll
            for (int mi = 0; mi < 4; mi++)
#pragma unroll
                for (int ni = 0; ni < 4; ni++)
                    mma_tf32(acc[mi][ni], afr[mi], bfr[ni]);
        }
        __syncthreads();
    }

    const int t  = t0 + nw;
    const int bc = 2 * (lane & 3);
#pragma unroll
    for (int mi = 0; mi < 4; mi++) {
        int g0 = mg0 + mw * 64 + mi * 16 + frag_r;
        float bias0 = dir ? (bihb[g0] + bhhb[g0]) : (bihf[g0] + bhhf[g0]);
        float bias1 = dir ? (bihb[g0 + 8] + bhhb[g0 + 8]) : (bihf[g0 + 8] + bhhf[g0 + 8]);
#pragma unroll
        for (int ni = 0; ni < 4; ni++) {
            int b = ni * 8 + bc;
            *(float2*)&g_xg[dir][t][g0][b] =
                make_float2(acc[mi][ni][0] + bias0, acc[mi][ni][1] + bias0);
            *(float2*)&g_xg[dir][t][g0 + 8][b] =
                make_float2(acc[mi][ni][2] + bias1, acc[mi][ni][3] + bias1);
        }
    }
}

// ---------------------------------------------------------------------------
// Grid barrier (all NB blocks co-resident; fenced monotonic counter)
// ---------------------------------------------------------------------------
__device__ __forceinline__ void grid_sync(unsigned target) {
    __threadfence();
    __syncthreads();
    if (threadIdx.x == 0) {
        atomicAdd((unsigned*)&g_bar, 1u);
        while (g_bar < target) { }
        __threadfence();
    }
    __syncthreads();
}

// ---------------------------------------------------------------------------
// Phase 2: persistent scan with bf16 split mma.
// 128 blocks = 2 dirs x 64 j-tiles(8). 256 threads = 8 warps.
// Per step per block: gates[32 m', 32 b] = Whh_blk[32, 512] @ h[512, 32]
//   m' = gate*8 + jj.  3-term: W0h0 + W0h1 + W1h0 (bf16 hi/lo planes).
// Warp tile m16n8: 8 warps = 2 m x 4 n. ldmatrix frags, pad-520 smem.
// Epilogue: +xg, LSTM cell per (jj,b) thread with c/h in registers.
// ---------------------------------------------------------------------------
// dynamic smem layout (bytes):
#define W0_OFF 0
#define W1_OFF 33280
#define H0_OFF 66560
#define H1_OFF 99840
#define CS_OFF 133120      // float [32][34]
#define HN_OFF 137472      // float [32][9]
#define SMEM_TOT 138624

__global__ __launch_bounds__(256, 1) void lstm_scan_kernel(
    const int*   __restrict__ lengths,
    const float* __restrict__ Whf,
    const float* __restrict__ Whb,
    float*       __restrict__ out)
{
    extern __shared__ __align__(16) char sm[];
    __nv_bfloat16* W0_s = (__nv_bfloat16*)(sm + W0_OFF);
    __nv_bfloat16* W1_s = (__nv_bfloat16*)(sm + W1_OFF);
    __nv_bfloat16* h0_s = (__nv_bfloat16*)(sm + H0_OFF);
    __nv_bfloat16* h1_s = (__nv_bfloat16*)(sm + H1_OFF);
    float* C_s  = (float*)(sm + CS_OFF);   // [32][34]
    float* hn_s = (float*)(sm + HN_OFF);   // [32][9]

    const int tid  = threadIdx.x;
    const int lane = tid & 31;
    const int wid  = tid >> 5;
    const int bx   = blockIdx.x;
    const int dir  = bx >> 6;
    const int j0   = (bx & 63) << 3;
    const float* W = dir ? Whb : Whf;

    // ---- stage W split into smem (once): row m' = gate*8+jj ----
#pragma unroll
    for (int i = 0; i < 16; i++) {
        int v = tid + i * 256;              // 0..4095
        int mrow = v >> 7;                  // 0..31
        int seg  = v & 127;                 // float4 index
        int gate = mrow >> 3, jj = mrow & 7;
        float4 wv = __ldg((const float4*)(W + (size_t)((gate << 9) + j0 + jj) * D_) + seg);
        __nv_bfloat16 h0 = __float2bfloat16_rn(wv.x);
        __nv_bfloat16 h1 = __float2bfloat16_rn(wv.y);
        __nv_bfloat16 h2 = __float2bfloat16_rn(wv.z);
        __nv_bfloat16 h3 = __float2bfloat16_rn(wv.w);
        __nv_bfloat16 l0 = __float2bfloat16_rn(wv.x - __bfloat162float(h0));
        __nv_bfloat16 l1 = __float2bfloat16_rn(wv.y - __bfloat162float(h1));
        __nv_bfloat16 l2 = __float2bfloat16_rn(wv.z - __bfloat162float(h2));
        __nv_bfloat16 l3 = __float2bfloat16_rn(wv.w - __bfloat162float(h3));
        uint32_t hA = (uint32_t)bfu(h0) | ((uint32_t)bfu(h1) << 16);
        uint32_t hB = (uint32_t)bfu(h2) | ((uint32_t)bfu(h3) << 16);
        uint32_t lA = (uint32_t)bfu(l0) | ((uint32_t)bfu(l1) << 16);
        uint32_t lB = (uint32_t)bfu(l2) | ((uint32_t)bfu(l3) << 16);
        int eoff = mrow * SH + seg * 4;     // element offset
        *(uint2*)((char*)W0_s + eoff * 2) = make_uint2(hA, hB);
        *(uint2*)((char*)W1_s + eoff * 2) = make_uint2(lA, lB);
    }

    // ldmatrix per-lane source offsets (bytes)
    const int wm = wid & 1, wn = wid >> 1;
    const int l8 = lane & 7, sel = lane >> 3;
    const uint32_t aoff =
        (uint32_t)(((wm * 16) + ((sel & 1) ? 8 : 0) + l8) * SH + ((sel >> 1) ? 8 : 0)) * 2;
    const uint32_t boff =
        (uint32_t)(((wn * 8) + l8) * SH + ((sel & 1) ? 8 : 0)) * 2;
    const uint32_t w0b = smem_u32(W0_s), w1b = smem_u32(W1_s);
    const uint32_t h0b = smem_u32(h0_s), h1b = smem_u32(h1_s);

    // epilogue identity: warp = jj, lane = b
    const int jj = wid, b = lane;
    const int len = __ldg(&lengths[b]);
    float c_reg = 0.f, h_reg = 0.f;
    int cur = 0;
    unsigned target = 0;

    for (int s = 0; s < T_; s++) {
        target += NB;
        grid_sync(target);

        // ---- stage h planes: 2048 uint4 per plane / 256 thr = 8 iters ----
        const uint4* s0 = (const uint4*)&g_h0[cur][dir][0][0];
        const uint4* s1 = (const uint4*)&g_h1[cur][dir][0][0];
#pragma unroll
        for (int i = 0; i < 8; i++) {
            int v = tid + i * 256;          // 0..2047
            int bb = v >> 6, seg = v & 63;  // seg: 8-elem group
            int eoff = bb * SH + seg * 8;
            *(uint4*)((char*)h0_s + eoff * 2) = __ldcg(s0 + v);
            *(uint4*)((char*)h1_s + eoff * 2) = __ldcg(s1 + v);
        }
        __syncthreads();

        const int t = dir ? (T_ - 1 - s) : s;

        // ---- prefetch xg for this thread's (jj,b) ----
        const float* xgp = &g_xg[dir][t][0][0];
        float xi = __ldg(xgp + (((0 << 9) + j0 + jj) << 5) + b);
        float xf = __ldg(xgp + (((1 << 9) + j0 + jj) << 5) + b);
        float xgv = __ldg(xgp + (((2 << 9) + j0 + jj) << 5) + b);
        float xo = __ldg(xgp + (((3 << 9) + j0 + jj) << 5) + b);

        // ---- mma mainloop: 32 k-steps of k16, 3 terms ----
        float c[4] = {0.f, 0.f, 0.f, 0.f};
#pragma unroll 8
        for (int ks = 0; ks < 32; ks++) {
            uint32_t koff = (uint32_t)(ks * 32);   // 16 elems * 2B
            uint32_t a0[4], a1[4], b0[2], b1[2];
            ldmx4(a0, w0b + aoff + koff);
            ldmx4(a1, w1b + aoff + koff);
            ldmx2(b0, h0b + boff + koff);
            ldmx2(b1, h1b + boff + koff);
            mma_bf16(c, a0, b0);
            mma_bf16(c, a0, b1);
            mma_bf16(c, a1, b0);
        }

        // ---- C frags -> C_s[m'][b] ----
        {
            int r = lane >> 2, cp = (lane & 3) * 2;
            *(float2*)&C_s[(wm * 16 + r) * 34 + wn * 8 + cp]     = make_float2(c[0], c[1]);
            *(float2*)&C_s[(wm * 16 + r + 8) * 34 + wn * 8 + cp] = make_float2(c[2], c[3]);
        }
        __syncthreads();

        // ---- LSTM cell for (jj, b) ----
        {
            float ri = C_s[(0 * 8 + jj) * 34 + b] + xi;
            float rf = C_s[(1 * 8 + jj) * 34 + b] + xf;
            float rg = C_s[(2 * 8 + jj) * 34 + b] + xgv;
            float ro = C_s[(3 * 8 + jj) * 34 + b] + xo;
            float ig = sigf(ri), fg = sigf(rf);
            float gg = tanhfast(rg), og = sigf(ro);
            float cn = fg * c_reg + ig * gg;
            float hn = og * tanhfast(cn);
            if (t < len) { c_reg = cn; h_reg = hn; }
            hn_s[b * 9 + jj] = h_reg;
        }
        __syncthreads();

        // ---- out store: 8 consecutive j per (b',t) ----
        {
            int bo = tid >> 3, jo = tid & 7;
            out[((size_t)bo * T_ + t) * (2 * H_) + (dir << 9) + j0 + jo] = hn_s[bo * 9 + jo];
        }
        // ---- pack h -> global bf16 planes (threads 0..63) ----
        if (tid < 64) {
            int bb = tid >> 1, q4 = (tid & 1) * 4;
            float v0 = hn_s[bb * 9 + q4 + 0];
            float v1 = hn_s[bb * 9 + q4 + 1];
            float v2 = hn_s[bb * 9 + q4 + 2];
            float v3 = hn_s[bb * 9 + q4 + 3];
            __nv_bfloat16 p0 = __float2bfloat16_rn(v0);
            __nv_bfloat16 p1 = __float2bfloat16_rn(v1);
            __nv_bfloat16 p2 = __float2bfloat16_rn(v2);
            __nv_bfloat16 p3 = __float2bfloat16_rn(v3);
            __nv_bfloat16 q0 = __float2bfloat16_rn(v0 - __bfloat162float(p0));
            __nv_bfloat16 q1 = __float2bfloat16_rn(v1 - __bfloat162float(p1));
            __nv_bfloat16 q2 = __float2bfloat16_rn(v2 - __bfloat162float(p2));
            __nv_bfloat16 q3 = __float2bfloat16_rn(v3 - __bfloat162float(p3));
            uint2 hw = make_uint2((uint32_t)bfu(p0) | ((uint32_t)bfu(p1) << 16),
                                  (uint32_t)bfu(p2) | ((uint32_t)bfu(p3) << 16));
            uint2 lw = make_uint2((uint32_t)bfu(q0) | ((uint32_t)bfu(q1) << 16),
                                  (uint32_t)bfu(q2) | ((uint32_t)bfu(q3) << 16));
            __stcg((uint2*)&g_h0[cur ^ 1][dir][bb][j0 + q4], hw);
            __stcg((uint2*)&g_h1[cur ^ 1][dir][bb][j0 + q4], lw);
        }
        cur ^= 1;
    }
}

// ---------------------------------------------------------------------------
extern "C" void kernel_launch(void* const* d_in, const int* in_sizes, int n_in,
                              void* d_out, int out_size)
{
    const float* x      = (const float*)d_in[0];
    const int*   lens   = (const int*)  d_in[1];
    const float* Wihf   = (const float*)d_in[2];
    const float* Whhf   = (const float*)d_in[3];
    const float* bihf   = (const float*)d_in[4];
    const float* bhhf   = (const float*)d_in[5];
    const float* Wihb   = (const float*)d_in[6];
    const float* Whhb   = (const float*)d_in[7];
    const float* bihb   = (const float*)d_in[8];
    const float* bhhb   = (const float*)d_in[9];
    float* out = (float*)d_out;

    cudaFuncSetAttribute(lstm_scan_kernel,
                         cudaFuncAttributeMaxDynamicSharedMemorySize, SMEM_TOT);

    dim3 pg(T_ / 4, 32);
    proj_mma_kernel<<<pg, 256>>>(x, Wihf, Wihb, bihf, bhhf, bihb, bhhb);

    lstm_scan_kernel<<<NB, 256, SMEM_TOT>>>(lens, Whhf, Whhb, out);
}